// round 1
// baseline (speedup 1.0000x reference)
#include <cuda_runtime.h>
#include <cstdint>

#define BATCH 256
#define DIM   2048
#define PNUM  56
#define NROWS (PNUM * BATCH)          // 14336
#define D4    (DIM / 4)               // 512 float4 per row

// log2(e)/T  with T=4
#define KEXP  0.3606737602222409f

// --- device scratch (no allocs allowed) ---
__device__ double       g_acc[2];             // [0]=soft_dil, [1]=soft_dcl (double accum)
__device__ unsigned int g_ctr;                // work counter for dcl
__device__ float        g_mean[BATCH * DIM];  // ebp_bar

__device__ __forceinline__ float ex2f(float x) {
    float r;
    asm("ex2.approx.ftz.f32 %0, %1;" : "=f"(r) : "f"(x));
    return r;
}

__global__ void k_init() {
    if (threadIdx.x < 2) g_acc[threadIdx.x] = 0.0;
    if (threadIdx.x == 0) g_ctr = 0u;
}

// ebp_bar[b,d] = mean_p ebp[p,b,d]; one thread per output float4
__global__ void k_mean(const float* __restrict__ ebp) {
    int tid = blockIdx.x * blockDim.x + threadIdx.x;    // 0 .. 131071
    int b  = tid >> 9;          // / 512
    int d4 = tid & 511;
    const float4* e4 = (const float4*)ebp;
    float sx = 0.f, sy = 0.f, sz = 0.f, sw = 0.f;
#pragma unroll 8
    for (int p = 0; p < PNUM; p++) {
        float4 v = e4[(p * BATCH + b) * D4 + d4];
        sx += v.x; sy += v.y; sz += v.z; sw += v.w;
    }
    const float inv = 1.0f / (float)PNUM;
    float4 o; o.x = sx * inv; o.y = sy * inv; o.z = sz * inv; o.w = sw * inv;
    ((float4*)g_mean)[tid] = o;
}

// soft_dil: per b: (T/D) * ( E_m[m-g] - E_g[m-g] ),  E_w = softmax(w/T)-weighted mean
__global__ void k_dil(const float* __restrict__ ebg) {
    int w    = (blockIdx.x * blockDim.x + threadIdx.x) >> 5;
    int lane = threadIdx.x & 31;
    if (w >= BATCH) return;
    const float4* g4 = (const float4*)(ebg    + (size_t)w * DIM);
    const float4* m4 = (const float4*)(g_mean + (size_t)w * DIM);
    float se_g = 0.f, se_m = 0.f, su_g = 0.f, su_m = 0.f;
#pragma unroll 4
    for (int i = 0; i < 16; i++) {
        float4 g = g4[i * 32 + lane];
        float4 m = m4[i * 32 + lane];
#define DIL1(c) { float u = m.c - g.c;                      \
                  float eg = ex2f(g.c * KEXP);              \
                  float em = ex2f(m.c * KEXP);              \
                  se_g += eg; se_m += em;                   \
                  su_g = fmaf(eg, u, su_g);                 \
                  su_m = fmaf(em, u, su_m); }
        DIL1(x) DIL1(y) DIL1(z) DIL1(w)
#undef DIL1
    }
#pragma unroll
    for (int off = 16; off; off >>= 1) {
        se_g += __shfl_xor_sync(0xffffffffu, se_g, off);
        se_m += __shfl_xor_sync(0xffffffffu, se_m, off);
        su_g += __shfl_xor_sync(0xffffffffu, su_g, off);
        su_m += __shfl_xor_sync(0xffffffffu, su_m, off);
    }
    if (lane == 0) {
        float kl = su_m / se_m - su_g / se_g;
        atomicAdd(&g_acc[0], (double)kl * (4.0 / (double)DIM));
    }
}

// soft_dcl: per row (item = p*B+b, which is exactly the ebp row index):
//   u = db - dg = (m-p)^2 - (g-p)^2 ; contribution (T/D)*(E_y[u] - E_x[u]) summed, /P
__global__ void __launch_bounds__(256) k_dcl(const float* __restrict__ ebg,
                                             const float* __restrict__ ebp) {
    int lane = threadIdx.x & 31;
    float local = 0.f;

    unsigned item = 0;
    if (lane == 0) item = atomicAdd(&g_ctr, 1u);
    item = __shfl_sync(0xffffffffu, item, 0);

    while (item < NROWS) {
        int b = (int)(item & (BATCH - 1));
        const float4* p4 = (const float4*)(ebp    + (size_t)item * DIM);
        const float4* g4 = (const float4*)(ebg    + (size_t)b    * DIM);
        const float4* m4 = (const float4*)(g_mean + (size_t)b    * DIM);

        float se_x = 0.f, se_y = 0.f, su_x = 0.f, su_y = 0.f;
#pragma unroll 4
        for (int i = 0; i < 16; i++) {
            float4 p = p4[i * 32 + lane];
            float4 g = g4[i * 32 + lane];
            float4 m = m4[i * 32 + lane];
#define DCL1(c) { float dg = g.c - p.c;                         \
                  float db = m.c - p.c;                         \
                  float u  = (db - dg) * (db + dg);             \
                  float ex = ex2f(dg * dg * KEXP);              \
                  float ey = ex2f(db * db * KEXP);              \
                  se_x += ex; se_y += ey;                       \
                  su_x = fmaf(ex, u, su_x);                     \
                  su_y = fmaf(ey, u, su_y); }
            DCL1(x) DCL1(y) DCL1(z) DCL1(w)
#undef DCL1
        }
#pragma unroll
        for (int off = 16; off; off >>= 1) {
            se_x += __shfl_xor_sync(0xffffffffu, se_x, off);
            se_y += __shfl_xor_sync(0xffffffffu, se_y, off);
            su_x += __shfl_xor_sync(0xffffffffu, su_x, off);
            su_y += __shfl_xor_sync(0xffffffffu, su_y, off);
        }
        local += su_y / se_y - su_x / se_x;

        if (lane == 0) item = atomicAdd(&g_ctr, 1u);
        item = __shfl_sync(0xffffffffu, item, 0);
    }
    if (lane == 0)
        atomicAdd(&g_acc[1], (double)local * (4.0 / ((double)DIM * (double)PNUM)));
}

__global__ void k_fin(float* __restrict__ out) {
    if (threadIdx.x == 0) {
        out[0] = (float)g_acc[0];
        out[1] = (float)g_acc[1];
    }
}

extern "C" void kernel_launch(void* const* d_in, const int* in_sizes, int n_in,
                              void* d_out, int out_size) {
    const float* ebg = (const float*)d_in[0];
    const float* ebp = (const float*)d_in[1];
    (void)in_sizes; (void)n_in;

    k_init<<<1, 32>>>();
    k_mean<<<512, 256>>>(ebp);                 // 131072 threads, 1 float4 each
    k_dil<<<32, 256>>>(ebg);                   // 256 warps, one per batch row
    k_dcl<<<592, 256>>>(ebg, ebp);             // 4 blocks/SM, warp-per-row via counter
    k_fin<<<1, 32>>>((float*)d_out);
}